// round 1
// baseline (speedup 1.0000x reference)
#include <cuda_runtime.h>
#include <mma.h>
#include <cstdint>

using namespace nvcuda;

// Problem constants (fixed by setup_inputs)
#define BATCH   16
#define SEQ     4096
#define TOKENS  (BATCH * SEQ)      // 65536
#define C_DIM   256
#define N_QKV   (3 * C_DIM)        // 768

// Scratch (allocation-free: __device__ globals)
__device__ float g_qkv[3ULL * TOKENS * N_QKV];     // [branch][token][768]
__device__ float g_comb[(size_t)TOKENS * C_DIM];   // [token][256]

// ---------------------------------------------------------------------------
// tf32 WMMA GEMM:  C = A(MxK, row-major) * B(KxN, row-major)
// Block tile 128x128, K-tile 32. 8 warps (2x4), warp tile 64x32 (4x2 frags).
// blockIdx.z selects a branch via bStrideZ / cStrideZ.
// ---------------------------------------------------------------------------
#define BM 128
#define BN 128
#define BK 32

__global__ __launch_bounds__(256) void gemm_tf32(
    const float* __restrict__ A, const float* __restrict__ B,
    float* __restrict__ Co, int M, int N, int K,
    size_t bStrideZ, size_t cStrideZ)
{
    __shared__ float As[BM][BK + 4];   // row stride 36 floats (16B aligned)
    __shared__ float Bs[BK][BN + 4];   // row stride 132 floats (16B aligned)

    const float* Bz = B + (size_t)blockIdx.z * bStrideZ;
    float*       Cz = Co + (size_t)blockIdx.z * cStrideZ;

    const int tileM = blockIdx.y;
    const int tileN = blockIdx.x;
    const int tid   = threadIdx.x;
    const int warp  = tid >> 5;
    const int wy    = warp >> 2;   // 0..1  (64 rows each)
    const int wx    = warp & 3;    // 0..3  (32 cols each)

    wmma::fragment<wmma::accumulator, 16, 16, 8, float> acc[4][2];
    #pragma unroll
    for (int i = 0; i < 4; i++)
        #pragma unroll
        for (int j = 0; j < 2; j++)
            wmma::fill_fragment(acc[i][j], 0.0f);

    for (int kt = 0; kt < K; kt += BK) {
        // Load A tile: 128x32 floats = 1024 float4, 4 per thread
        #pragma unroll
        for (int p = 0; p < 4; p++) {
            int idx = tid + p * 256;
            int r   = idx >> 3;
            int c4  = idx & 7;
            float4 v = *(const float4*)(A + (size_t)(tileM * BM + r) * K + kt + c4 * 4);
            *(float4*)(&As[r][c4 * 4]) = v;
        }
        // Load B tile: 32x128 floats = 1024 float4
        #pragma unroll
        for (int p = 0; p < 4; p++) {
            int idx = tid + p * 256;
            int r   = idx >> 5;
            int c4  = idx & 31;
            float4 v = *(const float4*)(Bz + (size_t)(kt + r) * N + tileN * BN + c4 * 4);
            *(float4*)(&Bs[r][c4 * 4]) = v;
        }
        __syncthreads();

        #pragma unroll
        for (int ks = 0; ks < BK; ks += 8) {
            wmma::fragment<wmma::matrix_a, 16, 16, 8, wmma::precision::tf32, wmma::row_major> af[4];
            wmma::fragment<wmma::matrix_b, 16, 16, 8, wmma::precision::tf32, wmma::row_major> bf[2];
            #pragma unroll
            for (int i = 0; i < 4; i++) {
                wmma::load_matrix_sync(af[i], &As[wy * 64 + i * 16][ks], BK + 4);
                #pragma unroll
                for (int e = 0; e < af[i].num_elements; e++)
                    af[i].x[e] = wmma::__float_to_tf32(af[i].x[e]);
            }
            #pragma unroll
            for (int j = 0; j < 2; j++) {
                wmma::load_matrix_sync(bf[j], &Bs[ks][wx * 32 + j * 16], BN + 4);
                #pragma unroll
                for (int e = 0; e < bf[j].num_elements; e++)
                    bf[j].x[e] = wmma::__float_to_tf32(bf[j].x[e]);
            }
            #pragma unroll
            for (int i = 0; i < 4; i++)
                #pragma unroll
                for (int j = 0; j < 2; j++)
                    wmma::mma_sync(acc[i][j], af[i], bf[j], acc[i][j]);
        }
        __syncthreads();
    }

    #pragma unroll
    for (int i = 0; i < 4; i++)
        #pragma unroll
        for (int j = 0; j < 2; j++) {
            int r0 = tileM * BM + wy * 64 + i * 16;
            int c0 = tileN * BN + wx * 32 + j * 16;
            wmma::store_matrix_sync(Cz + (size_t)r0 * N + c0, acc[i][j], N, wmma::mem_row_major);
        }
}

// ---------------------------------------------------------------------------
// Dilated local attention (K=3 taps, dilations 1,2,3), mean over 3 branches.
// One warp per token; lane owns 8 channels. Reads g_qkv, writes g_comb.
// Reference zero-pads: out-of-range taps contribute logit 0 and value 0.
// ---------------------------------------------------------------------------
__global__ __launch_bounds__(256) void attn_kernel()
{
    const int lane = threadIdx.x & 31;
    const int t    = blockIdx.x * 8 + (threadIdx.x >> 5);   // token
    const int n    = t & (SEQ - 1);                         // pos within batch
    const float scale = 0.0625f;                            // 256^-0.5

    float out[8];
    #pragma unroll
    for (int c = 0; c < 8; c++) out[c] = 0.0f;

    #pragma unroll
    for (int br = 0; br < 3; br++) {
        const int d = br + 1;
        const float* base = g_qkv + ((size_t)br * TOKENS + t) * N_QKV;

        float q[8];
        {
            float4 a = *(const float4*)(base + lane * 8);
            float4 b = *(const float4*)(base + lane * 8 + 4);
            q[0]=a.x; q[1]=a.y; q[2]=a.z; q[3]=a.w;
            q[4]=b.x; q[5]=b.y; q[6]=b.z; q[7]=b.w;
        }

        float lg[3];
        float vv[3][8];
        #pragma unroll
        for (int j = 0; j < 3; j++) {
            int off = (j - 1) * d;
            bool ok = ((unsigned)(n + off) < (unsigned)SEQ);
            float dot = 0.0f;
            if (ok) {
                const float* kr = base + (ptrdiff_t)off * N_QKV + C_DIM;
                float4 k0 = *(const float4*)(kr + lane * 8);
                float4 k1 = *(const float4*)(kr + lane * 8 + 4);
                dot = q[0]*k0.x + q[1]*k0.y + q[2]*k0.z + q[3]*k0.w
                    + q[4]*k1.x + q[5]*k1.y + q[6]*k1.z + q[7]*k1.w;
                const float* vr = base + (ptrdiff_t)off * N_QKV + 2 * C_DIM;
                float4 v0 = *(const float4*)(vr + lane * 8);
                float4 v1 = *(const float4*)(vr + lane * 8 + 4);
                vv[j][0]=v0.x; vv[j][1]=v0.y; vv[j][2]=v0.z; vv[j][3]=v0.w;
                vv[j][4]=v1.x; vv[j][5]=v1.y; vv[j][6]=v1.z; vv[j][7]=v1.w;
            } else {
                #pragma unroll
                for (int c = 0; c < 8; c++) vv[j][c] = 0.0f;
            }
            lg[j] = dot;   // 0 when out-of-range (zero-padded k row)
        }

        // Warp-reduce the three partial dot products
        #pragma unroll
        for (int s = 16; s > 0; s >>= 1) {
            lg[0] += __shfl_xor_sync(0xffffffffu, lg[0], s);
            lg[1] += __shfl_xor_sync(0xffffffffu, lg[1], s);
            lg[2] += __shfl_xor_sync(0xffffffffu, lg[2], s);
        }
        lg[0] *= scale; lg[1] *= scale; lg[2] *= scale;

        float m  = fmaxf(lg[0], fmaxf(lg[1], lg[2]));
        float e0 = expf(lg[0] - m);
        float e1 = expf(lg[1] - m);
        float e2 = expf(lg[2] - m);
        float inv = 1.0f / (e0 + e1 + e2);
        float a0 = e0 * inv, a1 = e1 * inv, a2 = e2 * inv;

        #pragma unroll
        for (int c = 0; c < 8; c++)
            out[c] += a0 * vv[0][c] + a1 * vv[1][c] + a2 * vv[2][c];
    }

    const float third = 1.0f / 3.0f;
    float4 o0, o1;
    o0.x = out[0]*third; o0.y = out[1]*third; o0.z = out[2]*third; o0.w = out[3]*third;
    o1.x = out[4]*third; o1.y = out[5]*third; o1.z = out[6]*third; o1.w = out[7]*third;
    float* dst = g_comb + (size_t)t * C_DIM + lane * 8;
    *(float4*)(dst)     = o0;
    *(float4*)(dst + 4) = o1;
}

// ---------------------------------------------------------------------------
// Bias add: out[m][c] += bproj[c]
// ---------------------------------------------------------------------------
__global__ __launch_bounds__(256) void bias_add(float* __restrict__ out,
                                                const float* __restrict__ b,
                                                size_t total)
{
    size_t i = (size_t)blockIdx.x * blockDim.x + threadIdx.x;
    size_t stride = (size_t)gridDim.x * blockDim.x;
    for (; i < total; i += stride)
        out[i] += b[i & (C_DIM - 1)];
}

// ---------------------------------------------------------------------------
// kernel_launch
// Inputs: d_in[0]=x (16,4096,256) f32, d_in[1]=Wqkv (3,256,768) f32,
//         d_in[2]=Wproj (256,256) f32, d_in[3]=bproj (256,) f32
// Output: (16,4096,256) f32
// ---------------------------------------------------------------------------
extern "C" void kernel_launch(void* const* d_in, const int* in_sizes, int n_in,
                              void* d_out, int out_size)
{
    const float* x     = (const float*)d_in[0];
    const float* Wqkv  = (const float*)d_in[1];
    const float* Wproj = (const float*)d_in[2];
    const float* bproj = (const float*)d_in[3];
    float*       out   = (float*)d_out;

    float* qkv  = nullptr;
    float* comb = nullptr;
    cudaGetSymbolAddress((void**)&qkv,  g_qkv);
    cudaGetSymbolAddress((void**)&comb, g_comb);

    // 1) QKV GEMM: 3 branches of (65536x256) @ (256x768)
    {
        dim3 grid(N_QKV / BN, TOKENS / BM, 3);
        gemm_tf32<<<grid, 256>>>(x, Wqkv, qkv, TOKENS, N_QKV, C_DIM,
                                 (size_t)C_DIM * N_QKV,
                                 (size_t)TOKENS * N_QKV);
    }

    // 2) Fused dilated local attention + mean over branches
    attn_kernel<<<TOKENS / 8, 256>>>();

    // 3) Proj GEMM: (65536x256) @ (256x256) -> out
    {
        dim3 grid(C_DIM / BN, TOKENS / BM, 1);
        gemm_tf32<<<grid, 256>>>(comb, Wproj, out, TOKENS, C_DIM, C_DIM, 0, 0);
    }

    // 4) Bias add
    bias_add<<<1024, 256>>>(out, bproj, (size_t)TOKENS * C_DIM);
}